// round 8
// baseline (speedup 1.0000x reference)
#include <cuda_runtime.h>
#include <cstdint>

// SuperpositionNeuron: out[r] = should_measure ? interfered[argmax(interfered+gumbel)]
//                                              : mean(interfered)
// interfered = sigmoid(x@W + b) @ M^T ;  B = 1048576, D = 128, S = 4.
//
// R8: cp.async (LDGSTS) pipeline. 3-stage ring of 16-column sub-tiles
// (3 x 16KB smem), gmem->smem directly (no register staging -> regs drop,
// 4 CTAs/SM). Persistent blocks keep the pipeline primed across tiles.
// smem layout [col][row] with row^(2*col) swizzle: conflict-free on both
// the cp.async store side and the per-row LDS.128 read side.

#define D_DIM     128
#define TILE_ROWS 256
#define RING      3

__constant__ float cW[512];   // [128][4] row-major
__constant__ float cM[16];    // [4][4]
__constant__ float cb[4];
__constant__ float cthr[1];

__device__ __forceinline__ uint32_t smem_u32(const void* p) {
    return (uint32_t)__cvta_generic_to_shared(p);
}
__device__ __forceinline__ void cp16(uint32_t dst, const void* src) {
    asm volatile("cp.async.cg.shared.global [%0], [%1], 16;\n"
                 :: "r"(dst), "l"(src) : "memory");
}
__device__ __forceinline__ void cp_commit() {
    asm volatile("cp.async.commit_group;\n" ::: "memory");
}
__device__ __forceinline__ void cp_wait1() {
    asm volatile("cp.async.wait_group 1;\n" ::: "memory");
}
__device__ __forceinline__ void cp_wait0() {
    asm volatile("cp.async.wait_group 0;\n" ::: "memory");
}

__global__ void __launch_bounds__(256, 4) sn_kernel(
    const float4* __restrict__ x4,      // [B,32] float4 view of x[B,128]
    const float*  __restrict__ noise,   // [B]
    const float*  __restrict__ u,       // [B]
    const float4* __restrict__ gumbel4, // [B]
    float* __restrict__ out,            // [B]
    int ntiles)
{
    // [stage][col j][row r] ; element (r,j) of a sub-tile stored at [j][r^(2j)]
    __shared__ float4 ring[RING][4][TILE_ROWS];   // 48 KB

    const int tid = threadIdx.x;
    // tiles for this block: blockIdx.x + k*gridDim.x, k = 0..nt-1
    const int nt = (ntiles - blockIdx.x + gridDim.x - 1) / gridDim.x;

    auto issue = [&](int k, int s, int b) {
        const long trow = (long)(blockIdx.x + k * (int)gridDim.x) * TILE_ROWS;
#pragma unroll
        for (int i = 0; i < 4; i++) {
            int f = i * 256 + tid, r = f >> 2, j = f & 3;
            cp16(smem_u32(&ring[b][j][r ^ (2 * j)]),
                 x4 + (trow + r) * 32 + s * 4 + j);
        }
        cp_commit();
    };

    // prologue: first two stages of this block's first tile
    issue(0, 0, 0);
    issue(0, 1, 1);

    int buf = 0;
    for (int k = 0; k < nt; k++) {
        const long trow = (long)(blockIdx.x + k * (int)gridDim.x) * TILE_ROWS;
        const long row  = trow + tid;

        // epilogue inputs: coalesced, issued ~8 stages before consumption
        float  nz = __ldg(noise + row);
        float  uu = __ldg(u + row);
        float4 g  = __ldg(gumbel4 + row);

        float acc0 = 0.f, acc1 = 0.f, acc2 = 0.f, acc3 = 0.f;

#pragma unroll
        for (int s = 0; s < 8; s++) {
            // stage (k,s) is the (g+1)-th committed group; with 2-deep issue
            // wait_group 1 guarantees it is complete, except at the very end.
            if (s == 7 && k == nt - 1) cp_wait0(); else cp_wait1();
            __syncthreads();

            // ---- compute: cols s*16 .. s*16+15 of this thread's row ----
#pragma unroll
            for (int cc = 0; cc < 4; cc++) {
                float4 xv = ring[buf][cc][tid ^ (2 * cc)];
                const float* w = &cW[(s * 4 + cc) * 16];  // W rows 4*(s*4+cc)..+3
                acc0 += xv.x * w[0] + xv.y * w[4] + xv.z * w[8]  + xv.w * w[12];
                acc1 += xv.x * w[1] + xv.y * w[5] + xv.z * w[9]  + xv.w * w[13];
                acc2 += xv.x * w[2] + xv.y * w[6] + xv.z * w[10] + xv.w * w[14];
                acc3 += xv.x * w[3] + xv.y * w[7] + xv.z * w[11] + xv.w * w[15];
            }

            // ---- issue stage g+2 into ring slot (buf+2)%3 ----
            // slot (buf+2)%3 was consumed at stage g-1; the barrier above
            // proves all threads are past it.
            int nk = k + (s >= 6 ? 1 : 0);
            int ns = (s + 2) & 7;
            if (nk < nt) issue(nk, ns, buf == 0 ? 2 : buf - 1);

            buf = (buf == 2) ? 0 : buf + 1;
        }

        // ---- dense epilogue (every lane = one row) ----
        float s0 = 1.f / (1.f + __expf(-(acc0 + cb[0])));
        float s1 = 1.f / (1.f + __expf(-(acc1 + cb[1])));
        float s2 = 1.f / (1.f + __expf(-(acc2 + cb[2])));
        float s3 = 1.f / (1.f + __expf(-(acc3 + cb[3])));

        float i0 = cM[0]  * s0 + cM[1]  * s1 + cM[2]  * s2 + cM[3]  * s3;
        float i1 = cM[4]  * s0 + cM[5]  * s1 + cM[6]  * s2 + cM[7]  * s3;
        float i2 = cM[8]  * s0 + cM[9]  * s1 + cM[10] * s2 + cM[11] * s3;
        float i3 = cM[12] * s0 + cM[13] * s1 + cM[14] * s2 + cM[15] * s3;

        float mp = 1.f / (1.f + __expf(-(nz + cthr[0])));
        bool should_measure = uu < mp;

        // gumbel-argmax (first-max tiebreak, matching jnp.argmax)
        float v0 = i0 + g.x, v1 = i1 + g.y, v2 = i2 + g.z, v3 = i3 + g.w;
        float best = v0, mv = i0;
        if (v1 > best) { best = v1; mv = i1; }
        if (v2 > best) { best = v2; mv = i2; }
        if (v3 > best) { best = v3; mv = i3; }

        float mean = 0.25f * (i0 + i1 + i2 + i3);
        __stcs(out + row, should_measure ? mv : mean);
    }
}

extern "C" void kernel_launch(void* const* d_in, const int* in_sizes, int n_in,
                              void* d_out, int out_size)
{
    const float* x      = (const float*)d_in[0];
    const float* W      = (const float*)d_in[1];
    const float* b      = (const float*)d_in[2];
    const float* M      = (const float*)d_in[3];
    const float* thr    = (const float*)d_in[4];
    const float* noise  = (const float*)d_in[5];
    const float* u      = (const float*)d_in[6];
    const float* gumbel = (const float*)d_in[7];
    float* out = (float*)d_out;

    // small uniform params -> constant bank (D2D async copies, capturable)
    cudaMemcpyToSymbolAsync(cW,   W,   512 * sizeof(float), 0, cudaMemcpyDeviceToDevice, 0);
    cudaMemcpyToSymbolAsync(cM,   M,    16 * sizeof(float), 0, cudaMemcpyDeviceToDevice, 0);
    cudaMemcpyToSymbolAsync(cb,   b,     4 * sizeof(float), 0, cudaMemcpyDeviceToDevice, 0);
    cudaMemcpyToSymbolAsync(cthr, thr,       sizeof(float), 0, cudaMemcpyDeviceToDevice, 0);

    int B = in_sizes[0] / D_DIM;              // 1048576
    int ntiles = B / TILE_ROWS;               // 4096
    int blocks = 608;                         // 4 CTAs/SM x 152 SMs, persistent
    if (blocks > ntiles) blocks = ntiles;
    sn_kernel<<<blocks, TILE_ROWS>>>((const float4*)x, noise, u,
                                     (const float4*)gumbel, out, ntiles);
}

// round 9
// speedup vs baseline: 1.8679x; 1.8679x over previous
#include <cuda_runtime.h>

// SuperpositionNeuron: out[r] = should_measure ? interfered[argmax(interfered+gumbel)]
//                                              : mean(interfered)
// interfered = sigmoid(x@W + b) @ M^T ;  B = 1048576, D = 128, S = 4.
//
// R9: R6 skeleton (LDG->reg->STS double-buffered transpose, one row per
// thread, W/M/b in __constant__) with 16-column sub-tiles: staging array
// halves (32->16 regs) and smem halves (64->32 KB) -> 4 CTAs/SM instead of 3.
// Swizzle: element j of row r stored at slot j ^ ((r>>1)&3); conflict-free
// on both STS.128 and LDS.128 phases (verified by bank walk).

#define D_DIM     128
#define TILE_ROWS 256
#define SUB_F4    4        // float4 per row per sub-tile (16 cols)

__constant__ float cW[512];   // [128][4] row-major
__constant__ float cM[16];    // [4][4]
__constant__ float cb[4];
__constant__ float cthr[1];

__global__ void __launch_bounds__(256, 4) sn_kernel(
    const float4* __restrict__ x4,      // [B, 32] float4 view of x[B,128]
    const float*  __restrict__ noise,   // [B]
    const float*  __restrict__ u,       // [B]
    const float4* __restrict__ gumbel4, // [B] float4 view of gumbel[B,4]
    float* __restrict__ out)            // [B]
{
    __shared__ float4 buf[2][TILE_ROWS * SUB_F4];   // 2 x 16 KB

    const int tid = threadIdx.x;
    const int tb  = blockIdx.x * TILE_ROWS;
    const int row = tb + tid;

    // ---- epilogue inputs: coalesced, prefetched up front ----
    float  nz = __ldg(noise + row);
    float  uu = __ldg(u + row);
    float4 g  = __ldg(gumbel4 + row);

    const int rx = (tid >> 1) & 3;   // XOR-swizzle key for this thread's row

    // ---- prologue: coop-load sub-tile 0 (cols 0..15) ----
    // f = i*256 + tid ; r = f>>2 ; j = f&3  -> warp covers 8 rows x 64B chunks
    float4 p[4];
#pragma unroll
    for (int i = 0; i < 4; i++) {
        int f = i * 256 + tid, r = f >> 2, j = f & 3;
        p[i] = __ldcs(x4 + (size_t)(tb + r) * 32 + j);
    }
#pragma unroll
    for (int i = 0; i < 4; i++) {
        int f = i * 256 + tid, r = f >> 2, j = f & 3;
        buf[0][r * 4 + (j ^ ((r >> 1) & 3))] = p[i];
    }
    __syncthreads();

    float acc0 = 0.f, acc1 = 0.f, acc2 = 0.f, acc3 = 0.f;

#pragma unroll
    for (int s = 0; s < 8; s++) {
        // prefetch next sub-tile into registers (overlaps compute below)
        if (s < 7) {
#pragma unroll
            for (int i = 0; i < 4; i++) {
                int f = i * 256 + tid, r = f >> 2, j = f & 3;
                p[i] = __ldcs(x4 + (size_t)(tb + r) * 32 + (s + 1) * 4 + j);
            }
        }

        // ---- compute: this thread's row, cols s*16 .. s*16+15 ----
        // Slot (cc^rx) holds element cc of this row; W indexed by cc
        // (compile-time uniform -> constant-bank loads).
#pragma unroll
        for (int cc = 0; cc < 4; cc++) {
            float4 xv = buf[s & 1][tid * 4 + (cc ^ rx)];
            const float* w = &cW[(s * 4 + cc) * 16];  // W rows 4*(s*4+cc)..+3
            acc0 += xv.x * w[0] + xv.y * w[4] + xv.z * w[8]  + xv.w * w[12];
            acc1 += xv.x * w[1] + xv.y * w[5] + xv.z * w[9]  + xv.w * w[13];
            acc2 += xv.x * w[2] + xv.y * w[6] + xv.z * w[10] + xv.w * w[14];
            acc3 += xv.x * w[3] + xv.y * w[7] + xv.z * w[11] + xv.w * w[15];
        }

        // stage next sub-tile into the other buffer
        if (s < 7) {
            __syncthreads();   // everyone done reading buf[(s+1)&1] last stage
#pragma unroll
            for (int i = 0; i < 4; i++) {
                int f = i * 256 + tid, r = f >> 2, j = f & 3;
                buf[(s + 1) & 1][r * 4 + (j ^ ((r >> 1) & 3))] = p[i];
            }
            __syncthreads();
        }
    }

    // ---- dense epilogue (every lane = one row) ----
    float s0 = 1.f / (1.f + __expf(-(acc0 + cb[0])));
    float s1 = 1.f / (1.f + __expf(-(acc1 + cb[1])));
    float s2 = 1.f / (1.f + __expf(-(acc2 + cb[2])));
    float s3 = 1.f / (1.f + __expf(-(acc3 + cb[3])));

    float i0 = cM[0]  * s0 + cM[1]  * s1 + cM[2]  * s2 + cM[3]  * s3;
    float i1 = cM[4]  * s0 + cM[5]  * s1 + cM[6]  * s2 + cM[7]  * s3;
    float i2 = cM[8]  * s0 + cM[9]  * s1 + cM[10] * s2 + cM[11] * s3;
    float i3 = cM[12] * s0 + cM[13] * s1 + cM[14] * s2 + cM[15] * s3;

    float mp = 1.f / (1.f + __expf(-(nz + cthr[0])));
    bool should_measure = uu < mp;

    // gumbel-argmax (first-max tiebreak, matching jnp.argmax)
    float v0 = i0 + g.x, v1 = i1 + g.y, v2 = i2 + g.z, v3 = i3 + g.w;
    float best = v0, mv = i0;
    if (v1 > best) { best = v1; mv = i1; }
    if (v2 > best) { best = v2; mv = i2; }
    if (v3 > best) { best = v3; mv = i3; }

    float mean = 0.25f * (i0 + i1 + i2 + i3);
    __stcs(out + row, should_measure ? mv : mean);
}

extern "C" void kernel_launch(void* const* d_in, const int* in_sizes, int n_in,
                              void* d_out, int out_size)
{
    const float* x      = (const float*)d_in[0];
    const float* W      = (const float*)d_in[1];
    const float* b      = (const float*)d_in[2];
    const float* M      = (const float*)d_in[3];
    const float* thr    = (const float*)d_in[4];
    const float* noise  = (const float*)d_in[5];
    const float* u      = (const float*)d_in[6];
    const float* gumbel = (const float*)d_in[7];
    float* out = (float*)d_out;

    // small uniform params -> constant bank (D2D async copies, capturable)
    cudaMemcpyToSymbolAsync(cW,   W,   512 * sizeof(float), 0, cudaMemcpyDeviceToDevice, 0);
    cudaMemcpyToSymbolAsync(cM,   M,    16 * sizeof(float), 0, cudaMemcpyDeviceToDevice, 0);
    cudaMemcpyToSymbolAsync(cb,   b,     4 * sizeof(float), 0, cudaMemcpyDeviceToDevice, 0);
    cudaMemcpyToSymbolAsync(cthr, thr,       sizeof(float), 0, cudaMemcpyDeviceToDevice, 0);

    int B = in_sizes[0] / D_DIM;              // 1048576
    int blocks = B / TILE_ROWS;               // 4096
    sn_kernel<<<blocks, TILE_ROWS>>>((const float4*)x, noise, u,
                                     (const float4*)gumbel, out);
}